// round 9
// baseline (speedup 1.0000x reference)
#include <cuda_runtime.h>
#include <cuda_bf16.h>
#include <cstdint>

#define N_NODES 50000
#define E_EDGES 600000
#define IN_DIM  256
#define OUT_DIM 128
#define SCALE   1.8f
#define ALPHA   0.15f
#define ONE_MA  0.85f

// ---------------------------------------------------------------- scratch
__device__ float g_h[(size_t)N_NODES * OUT_DIM];
__device__ float g_z[(size_t)N_NODES * OUT_DIM];
__device__ __align__(16) int g_indeg[N_NODES];
__device__ int   g_off[N_NODES + 1];
__device__ int   g_cursor[N_NODES];
__device__ float g_dinv[N_NODES];
__device__ uint2 g_edge[E_EDGES];          // packed (src, weight)
__device__ __nv_bfloat16 g_whi[(size_t)OUT_DIM * IN_DIM];
__device__ __nv_bfloat16 g_wlo[(size_t)OUT_DIM * IN_DIM];

// ---------------------------------------------------------------- helpers
__device__ __forceinline__ uint32_t smem_u32(const void* p) {
    uint32_t a;
    asm("{ .reg .u64 t; cvta.to.shared.u64 t, %1; cvt.u32.u64 %0, t; }" : "=r"(a) : "l"(p));
    return a;
}
__device__ __forceinline__ void ldsm_x4(uint32_t* r, uint32_t addr) {
    asm volatile("ldmatrix.sync.aligned.m8n8.x4.shared.b16 {%0,%1,%2,%3}, [%4];"
                 : "=r"(r[0]), "=r"(r[1]), "=r"(r[2]), "=r"(r[3]) : "r"(addr));
}
__device__ __forceinline__ void mma_bf16(float* c, const uint32_t* a, const uint32_t* b) {
    asm volatile("mma.sync.aligned.m16n8k16.row.col.f32.bf16.bf16.f32 "
                 "{%0,%1,%2,%3}, {%4,%5,%6,%7}, {%8,%9}, {%0,%1,%2,%3};"
                 : "+f"(c[0]), "+f"(c[1]), "+f"(c[2]), "+f"(c[3])
                 : "r"(a[0]), "r"(a[1]), "r"(a[2]), "r"(a[3]), "r"(b[0]), "r"(b[1]));
}
__device__ __forceinline__ void split2(float x, float y,
                                       __nv_bfloat162& hi, __nv_bfloat162& lo) {
    __nv_bfloat16 hx = __float2bfloat16(x), hy = __float2bfloat16(y);
    __nv_bfloat16 lx = __float2bfloat16(x - __bfloat162float(hx));
    __nv_bfloat16 ly = __float2bfloat16(y - __bfloat162float(hy));
    hi = __halves2bfloat162(hx, hy);
    lo = __halves2bfloat162(lx, ly);
}
__device__ __forceinline__ void cp_async16(uint32_t s, const void* g) {
    asm volatile("cp.async.ca.shared.global [%0], [%1], 16;" :: "r"(s), "l"(g));
}
__device__ __forceinline__ void cp_async16z(uint32_t s, const void* g, int valid) {
    asm volatile("cp.async.ca.shared.global [%0], [%1], 16, %2;"
                 :: "r"(s), "l"(g), "r"(valid ? 16 : 0));
}
#define CP_COMMIT()  asm volatile("cp.async.commit_group;" ::: "memory")
#define CP_WAIT(n)   asm volatile("cp.async.wait_group %0;" :: "n"(n) : "memory")

// ---------------------------------------------------------------- W pre-split
__global__ void k_wsplit(const float* __restrict__ W) {
    int i = blockIdx.x * blockDim.x + threadIdx.x;     // pair index
    if (i * 2 >= OUT_DIM * IN_DIM) return;
    float2 v = ((const float2*)W)[i];
    __nv_bfloat16 hx = __float2bfloat16(v.x), hy = __float2bfloat16(v.y);
    __nv_bfloat16 lx = __float2bfloat16(v.x - __bfloat162float(hx));
    __nv_bfloat16 ly = __float2bfloat16(v.y - __bfloat162float(hy));
    ((__nv_bfloat162*)g_whi)[i] = __halves2bfloat162(hx, hy);
    ((__nv_bfloat162*)g_wlo)[i] = __halves2bfloat162(lx, ly);
}

// ---------------------------------------------------------------- graph-norm build
__global__ void k_deg(const int* __restrict__ ei) {
    int e = (blockIdx.x * blockDim.x + threadIdx.x) * 2;   // E even
    if (e < E_EDGES) {
        int2 c2 = *(const int2*)(ei + E_EDGES + e);
        atomicAdd(&g_indeg[c2.x], 1);
        atomicAdd(&g_indeg[c2.y], 1);
    }
}
// single-block exclusive scan, 4 elems/thread (int4), fused dinv
__global__ void __launch_bounds__(1024) k_scan() {
    __shared__ int wsum[32];
    int lane = threadIdx.x & 31, wid = threadIdx.x >> 5;
    int carry = 0;
    for (int base = 0; base < N_NODES; base += 4096) {
        int i4 = base + threadIdx.x * 4;
        int4 v = make_int4(0, 0, 0, 0);
        if (i4 < N_NODES) v = *(const int4*)(g_indeg + i4);   // N%4==0: full or none
        int vs = v.x + v.y + v.z + v.w;
        int x = vs;
#pragma unroll
        for (int d = 1; d < 32; d <<= 1) {
            int y = __shfl_up_sync(0xFFFFFFFFu, x, d);
            if (lane >= d) x += y;
        }
        if (lane == 31) wsum[wid] = x;
        __syncthreads();
        if (wid == 0) {
            int w = wsum[lane];
#pragma unroll
            for (int d = 1; d < 32; d <<= 1) {
                int y = __shfl_up_sync(0xFFFFFFFFu, w, d);
                if (lane >= d) w += y;
            }
            wsum[lane] = w;
        }
        __syncthreads();
        int excl = x - vs + (wid > 0 ? wsum[wid - 1] : 0) + carry;
        if (i4 < N_NODES) {
            int e0 = excl;
            int e1 = e0 + v.x;
            int e2 = e1 + v.y;
            int e3 = e2 + v.z;
            g_off[i4] = e0;     g_cursor[i4] = e0;
            g_off[i4 + 1] = e1; g_cursor[i4 + 1] = e1;
            g_off[i4 + 2] = e2; g_cursor[i4 + 2] = e2;
            g_off[i4 + 3] = e3; g_cursor[i4 + 3] = e3;
            g_dinv[i4]     = rsqrtf((float)(v.x + 1));
            g_dinv[i4 + 1] = rsqrtf((float)(v.y + 1));
            g_dinv[i4 + 2] = rsqrtf((float)(v.z + 1));
            g_dinv[i4 + 3] = rsqrtf((float)(v.w + 1));
        }
        carry += wsum[31];
        __syncthreads();
    }
    if (threadIdx.x == 0) g_off[N_NODES] = E_EDGES;
}
__global__ void k_place(const int* __restrict__ ei) {
    int e = (blockIdx.x * blockDim.x + threadIdx.x) * 2;   // E even
    if (e < E_EDGES) {
        int2 r2 = *(const int2*)(ei + e);
        int2 c2 = *(const int2*)(ei + E_EDGES + e);
        float dr0 = g_dinv[r2.x], dc0 = g_dinv[c2.x];
        float dr1 = g_dinv[r2.y], dc1 = g_dinv[c2.y];
        int p0 = atomicAdd(&g_cursor[c2.x], 1);
        g_edge[p0] = make_uint2((uint32_t)r2.x, __float_as_uint(dr0 * dc0));
        int p1 = atomicAdd(&g_cursor[c2.y], 1);
        g_edge[p1] = make_uint2((uint32_t)r2.y, __float_as_uint(dr1 * dc1));
    }
}

// ---------------------------------------------------------------- HMMA GEMM
// h = normalize(x @ W^T + b) * SCALE via bf16 2-split (hi*hi + hi*lo + lo*hi).
// cp.async double-buffered staging of X (fp32) and pre-split W (bf16).
// CTA 128x128, 8 warps (32m x 64n), m16n8k16; 2 CTAs/SM; dynamic smem.
#define RS 40
#define XROW  36                              // fp32 row stride (144 B)
#define XBUF  (128 * XROW * 4)                // 18432 B per buffer
#define BBUF  (128 * RS * 2)                  // 10240 B per buffer
#define OFF_XF   0
#define OFF_BHI  (OFF_XF  + 2 * XBUF)         // 36864
#define OFF_BLO  (OFF_BHI + 2 * BBUF)         // 57344
#define OFF_AHI  (OFF_BLO + 2 * BBUF)         // 77824
#define OFF_ALO  (OFF_AHI + BBUF)             // 88064
#define OFF_BIAS (OFF_ALO + BBUF)             // 98304
#define OFF_SSQ  (OFF_BIAS + 512)             // 98816
#define SMEM_TOTAL (OFF_SSQ + 128 * 2 * 4)    // 99840

__device__ __forceinline__ void gemm_prefetch(int step, int buf, int row0,
                                              const float* __restrict__ X,
                                              uint32_t smb, int tid) {
    int k0 = step * 32;
    uint32_t xbase = smb + OFF_XF + buf * XBUF;
#pragma unroll
    for (int t = tid; t < 1024; t += 256) {
        int r = t >> 3, j = t & 7;
        int gr = row0 + r;
        int ok = gr < N_NODES;
        const float* src = X + (size_t)(ok ? gr : 0) * IN_DIM + k0 + j * 4;
        cp_async16z(xbase + r * (XROW * 4) + j * 16, src, ok);
    }
    uint32_t hbase = smb + OFF_BHI + buf * BBUF;
    uint32_t lbase = smb + OFF_BLO + buf * BBUF;
#pragma unroll
    for (int t = tid; t < 1024; t += 256) {
        int arr = t >> 9;
        int u = t & 511;
        int r = u >> 2, j = u & 3;
        const __nv_bfloat16* wsrc = (arr ? g_wlo : g_whi) + (size_t)r * IN_DIM + k0 + j * 8;
        cp_async16((arr ? lbase : hbase) + r * (RS * 2) + j * 16, wsrc);
    }
    CP_COMMIT();
}

__global__ void __launch_bounds__(256, 2) k_gemm_mma(const float* __restrict__ X,
                                                     const float* __restrict__ B) {
    extern __shared__ char sm[];
    uint32_t smb = smem_u32(sm);
    float* s_bias = (float*)(sm + OFF_BIAS);
    float (*s_ssq)[2] = (float(*)[2])(sm + OFF_SSQ);

    int tid = threadIdx.x, lane = tid & 31, wid = tid >> 5;
    int warp_m = wid & 3, warp_n = wid >> 2;
    int row0 = blockIdx.x * 128;
    if (tid < OUT_DIM) s_bias[tid] = B[tid];

    uint32_t aAhi = smb + OFF_AHI, aAlo = smb + OFF_ALO;

    float c[2][8][4];
#pragma unroll
    for (int mi = 0; mi < 2; mi++)
#pragma unroll
        for (int nj = 0; nj < 8; nj++)
#pragma unroll
            for (int q = 0; q < 4; q++) c[mi][nj][q] = 0.f;

    uint32_t a_row = lane & 15;
    uint32_t a_kh  = lane >> 4;
    uint32_t b_g   = lane >> 3;
    uint32_t b_ln  = lane & 7;

    gemm_prefetch(0, 0, row0, X, smb, tid);

    for (int step = 0; step < 8; step++) {
        int buf = step & 1;
        if (step < 7) {
            gemm_prefetch(step + 1, buf ^ 1, row0, X, smb, tid);
            CP_WAIT(1);
        } else {
            CP_WAIT(0);
        }
        __syncthreads();

        // split phase: fp32 X tile (smem) -> bf16 hi/lo tiles (smem)
        const float* xf = (const float*)(sm + OFF_XF + buf * XBUF);
#pragma unroll
        for (int t = tid; t < 1024; t += 256) {
            int r  = t >> 3;
            int cc = (t & 7) << 2;
            float4 xv = *(const float4*)(xf + r * XROW + cc);
            __nv_bfloat162 h01, h23, l01, l23;
            split2(xv.x, xv.y, h01, l01);
            split2(xv.z, xv.w, h23, l23);
            int so = (r * RS + cc) * 2;
            *(__nv_bfloat162*)(sm + OFF_AHI + so)     = h01;
            *(__nv_bfloat162*)(sm + OFF_AHI + so + 4) = h23;
            *(__nv_bfloat162*)(sm + OFF_ALO + so)     = l01;
            *(__nv_bfloat162*)(sm + OFF_ALO + so + 4) = l23;
        }
        __syncthreads();

        uint32_t aBhi = smb + OFF_BHI + buf * BBUF;
        uint32_t aBlo = smb + OFF_BLO + buf * BBUF;
#pragma unroll
        for (int kk = 0; kk < 32; kk += 16) {
            uint32_t ah[2][4], al[2][4];
#pragma unroll
            for (int mi = 0; mi < 2; mi++) {
                uint32_t off = (uint32_t)(warp_m * 32 + mi * 16 + a_row) * (RS * 2)
                             + (kk + a_kh * 8) * 2;
                ldsm_x4(ah[mi], aAhi + off);
                ldsm_x4(al[mi], aAlo + off);
            }
#pragma unroll
            for (int njp = 0; njp < 4; njp++) {
                uint32_t row = (uint32_t)(warp_n * 64 + njp * 16 + (b_g >> 1) * 8 + b_ln);
                uint32_t off = row * (RS * 2) + (kk + (b_g & 1) * 8) * 2;
                uint32_t bh[4], bl[4];
                ldsm_x4(bh, aBhi + off);
                ldsm_x4(bl, aBlo + off);
#pragma unroll
                for (int mi = 0; mi < 2; mi++) {
                    mma_bf16(c[mi][njp * 2],     ah[mi], bh);
                    mma_bf16(c[mi][njp * 2],     ah[mi], bl);
                    mma_bf16(c[mi][njp * 2],     al[mi], bh);
                    mma_bf16(c[mi][njp * 2 + 1], ah[mi], bh + 2);
                    mma_bf16(c[mi][njp * 2 + 1], ah[mi], bl + 2);
                    mma_bf16(c[mi][njp * 2 + 1], al[mi], bh + 2);
                }
            }
        }
        __syncthreads();
    }

    // epilogue: bias, row L2-norm across two warp_n halves, scale, store
    int qr = lane >> 2;
    int qc = (lane & 3) * 2;
    float sq[2][2] = {{0.f, 0.f}, {0.f, 0.f}};
#pragma unroll
    for (int mi = 0; mi < 2; mi++)
#pragma unroll
        for (int nj = 0; nj < 8; nj++) {
            int colb = warp_n * 64 + nj * 8 + qc;
            float b0 = s_bias[colb], b1 = s_bias[colb + 1];
            c[mi][nj][0] += b0; c[mi][nj][1] += b1;
            c[mi][nj][2] += b0; c[mi][nj][3] += b1;
            sq[mi][0] += c[mi][nj][0] * c[mi][nj][0] + c[mi][nj][1] * c[mi][nj][1];
            sq[mi][1] += c[mi][nj][2] * c[mi][nj][2] + c[mi][nj][3] * c[mi][nj][3];
        }
#pragma unroll
    for (int mi = 0; mi < 2; mi++)
#pragma unroll
        for (int h = 0; h < 2; h++) {
            float v = sq[mi][h];
            v += __shfl_xor_sync(0xFFFFFFFFu, v, 1);
            v += __shfl_xor_sync(0xFFFFFFFFu, v, 2);
            if ((lane & 3) == 0)
                s_ssq[warp_m * 32 + mi * 16 + h * 8 + qr][warp_n] = v;
        }
    __syncthreads();
#pragma unroll
    for (int mi = 0; mi < 2; mi++)
#pragma unroll
        for (int h = 0; h < 2; h++) {
            int rloc = warp_m * 32 + mi * 16 + h * 8 + qr;
            float tot = s_ssq[rloc][0] + s_ssq[rloc][1];
            float s = SCALE / fmaxf(sqrtf(tot), 1e-12f);
            int gr = row0 + rloc;
            if (gr < N_NODES) {
                float* o = g_h + (size_t)gr * OUT_DIM + warp_n * 64 + qc;
#pragma unroll
                for (int nj = 0; nj < 8; nj++) {
                    float2 w2;
                    w2.x = c[mi][nj][h * 2] * s;
                    w2.y = c[mi][nj][h * 2 + 1] * s;
                    *(float2*)(o + nj * 8) = w2;
                }
            }
        }
}

// ---------------------------------------------------------------- gather rounds
__global__ void __launch_bounds__(256) k_gather1() {
    int n = blockIdx.x * 8 + (threadIdx.x >> 5);
    int lane = threadIdx.x & 31;
    if (n >= N_NODES) return;

    int e0 = g_off[n], e1 = g_off[n + 1];
    float4 acc = make_float4(0.f, 0.f, 0.f, 0.f);
#pragma unroll 4
    for (int e = e0; e < e1; e++) {
        uint2 ed = g_edge[e];
        float w = __uint_as_float(ed.y);
        float4 v = __ldg((const float4*)(g_h + (size_t)ed.x * OUT_DIM) + lane);
        acc.x += w * v.x; acc.y += w * v.y; acc.z += w * v.z; acc.w += w * v.w;
    }
    float dn = g_dinv[n];
    float sc = ONE_MA * dn * dn + ALPHA;
    float4 hh = __ldg((const float4*)(g_h + (size_t)n * OUT_DIM) + lane);
    float4 o;
    o.x = ONE_MA * acc.x + sc * hh.x;
    o.y = ONE_MA * acc.y + sc * hh.y;
    o.z = ONE_MA * acc.z + sc * hh.z;
    o.w = ONE_MA * acc.w + sc * hh.w;
    *((float4*)(g_z + (size_t)n * OUT_DIM) + lane) = o;
}

__global__ void __launch_bounds__(256) k_gather2(float* __restrict__ out) {
    int n = blockIdx.x * 8 + (threadIdx.x >> 5);
    int lane = threadIdx.x & 31;
    if (n >= N_NODES) return;

    int e0 = g_off[n], e1 = g_off[n + 1];
    float4 acc = make_float4(0.f, 0.f, 0.f, 0.f);
#pragma unroll 4
    for (int e = e0; e < e1; e++) {
        uint2 ed = g_edge[e];
        float w = __uint_as_float(ed.y);
        float4 v = __ldg((const float4*)(g_z + (size_t)ed.x * OUT_DIM) + lane);
        acc.x += w * v.x; acc.y += w * v.y; acc.z += w * v.z; acc.w += w * v.w;
    }
    float dn = g_dinv[n];
    float sw = dn * dn;
    float4 cur = __ldg((const float4*)(g_z + (size_t)n * OUT_DIM) + lane);
    float4 hh  = __ldg((const float4*)(g_h + (size_t)n * OUT_DIM) + lane);
    float4 o;
    o.x = ONE_MA * (acc.x + sw * cur.x) + ALPHA * hh.x;
    o.y = ONE_MA * (acc.y + sw * cur.y) + ALPHA * hh.y;
    o.z = ONE_MA * (acc.z + sw * cur.z) + ALPHA * hh.z;
    o.w = ONE_MA * (acc.w + sw * cur.w) + ALPHA * hh.w;
    *((float4*)(out + (size_t)n * OUT_DIM) + lane) = o;
}

// ----------------------------------------------------------------
extern "C" void kernel_launch(void* const* d_in, const int* in_sizes, int n_in,
                              void* d_out, int out_size) {
    const float* x  = (const float*)d_in[0];
    const int*   ei = (const int*)d_in[1];
    const float* W  = (const float*)d_in[2];
    const float* b  = (const float*)d_in[3];
    float* out = (float*)d_out;

    // one-time side-stream + events + symbol address (host resources only)
    static cudaStream_t s2 = nullptr;
    static cudaEvent_t ev_fork = nullptr, ev_w = nullptr, ev_join = nullptr;
    static void* indeg_ptr = nullptr;
    if (s2 == nullptr) {
        cudaStreamCreateWithFlags(&s2, cudaStreamNonBlocking);
        cudaEventCreateWithFlags(&ev_fork, cudaEventDisableTiming);
        cudaEventCreateWithFlags(&ev_w, cudaEventDisableTiming);
        cudaEventCreateWithFlags(&ev_join, cudaEventDisableTiming);
        cudaGetSymbolAddress(&indeg_ptr, g_indeg);
        cudaFuncSetAttribute(k_gemm_mma,
                             cudaFuncAttributeMaxDynamicSharedMemorySize, SMEM_TOTAL);
    }

    // fork: wsplit + CSR build on s2, GEMM on the main (capture) stream
    cudaEventRecord(ev_fork, 0);
    cudaStreamWaitEvent(s2, ev_fork, 0);

    k_wsplit<<<(OUT_DIM * IN_DIM / 2 + 255) / 256, 256, 0, s2>>>(W);
    cudaEventRecord(ev_w, s2);
    cudaMemsetAsync(indeg_ptr, 0, N_NODES * sizeof(int), s2);
    k_deg  <<<(E_EDGES / 2 + 255) / 256, 256, 0, s2>>>(ei);
    k_scan <<<1, 1024, 0, s2>>>();
    k_place<<<(E_EDGES / 2 + 255) / 256, 256, 0, s2>>>(ei);
    cudaEventRecord(ev_join, s2);

    cudaStreamWaitEvent(0, ev_w, 0);
    k_gemm_mma<<<(N_NODES + 127) / 128, 256, SMEM_TOTAL>>>(x, b);

    // join: gathers need both the GEMM (g_h) and the CSR build
    cudaStreamWaitEvent(0, ev_join, 0);
    k_gather1<<<(N_NODES + 7) / 8, 256>>>();
    k_gather2<<<(N_NODES + 7) / 8, 256>>>(out);
}

// round 10
// speedup vs baseline: 1.0622x; 1.0622x over previous
#include <cuda_runtime.h>
#include <cuda_bf16.h>
#include <cuda_fp16.h>
#include <cstdint>

#define N_NODES 50000
#define E_EDGES 600000
#define IN_DIM  256
#define OUT_DIM 128
#define SCALE   1.8f
#define ALPHA   0.15f
#define ONE_MA  0.85f

// ---------------------------------------------------------------- scratch
__device__ float g_h[(size_t)N_NODES * OUT_DIM];
__device__ float g_z[(size_t)N_NODES * OUT_DIM];
__device__ __half g_h16[(size_t)N_NODES * OUT_DIM];   // fp16 mirror for gather reads
__device__ __half g_z16[(size_t)N_NODES * OUT_DIM];
__device__ __align__(16) int g_indeg[N_NODES];
__device__ int   g_off[N_NODES + 1];
__device__ int   g_cursor[N_NODES];
__device__ float g_dinv[N_NODES];
__device__ uint2 g_edge[E_EDGES];          // packed (src, weight)
__device__ __nv_bfloat16 g_whi[(size_t)OUT_DIM * IN_DIM];
__device__ __nv_bfloat16 g_wlo[(size_t)OUT_DIM * IN_DIM];

// ---------------------------------------------------------------- helpers
__device__ __forceinline__ uint32_t smem_u32(const void* p) {
    uint32_t a;
    asm("{ .reg .u64 t; cvta.to.shared.u64 t, %1; cvt.u32.u64 %0, t; }" : "=r"(a) : "l"(p));
    return a;
}
__device__ __forceinline__ void ldsm_x4(uint32_t* r, uint32_t addr) {
    asm volatile("ldmatrix.sync.aligned.m8n8.x4.shared.b16 {%0,%1,%2,%3}, [%4];"
                 : "=r"(r[0]), "=r"(r[1]), "=r"(r[2]), "=r"(r[3]) : "r"(addr));
}
__device__ __forceinline__ void mma_bf16(float* c, const uint32_t* a, const uint32_t* b) {
    asm volatile("mma.sync.aligned.m16n8k16.row.col.f32.bf16.bf16.f32 "
                 "{%0,%1,%2,%3}, {%4,%5,%6,%7}, {%8,%9}, {%0,%1,%2,%3};"
                 : "+f"(c[0]), "+f"(c[1]), "+f"(c[2]), "+f"(c[3])
                 : "r"(a[0]), "r"(a[1]), "r"(a[2]), "r"(a[3]), "r"(b[0]), "r"(b[1]));
}
__device__ __forceinline__ void split2(float x, float y,
                                       __nv_bfloat162& hi, __nv_bfloat162& lo) {
    __nv_bfloat16 hx = __float2bfloat16(x), hy = __float2bfloat16(y);
    __nv_bfloat16 lx = __float2bfloat16(x - __bfloat162float(hx));
    __nv_bfloat16 ly = __float2bfloat16(y - __bfloat162float(hy));
    hi = __halves2bfloat162(hx, hy);
    lo = __halves2bfloat162(lx, ly);
}
// fp16x4 (uint2) -> float4 accumulate helper
__device__ __forceinline__ void acc_h4(float4& acc, float w, uint2 pk) {
    __half2 p0 = *reinterpret_cast<__half2*>(&pk.x);
    __half2 p1 = *reinterpret_cast<__half2*>(&pk.y);
    float2 f0 = __half22float2(p0);
    float2 f1 = __half22float2(p1);
    acc.x += w * f0.x; acc.y += w * f0.y;
    acc.z += w * f1.x; acc.w += w * f1.y;
}

// ---------------------------------------------------------------- W pre-split
__global__ void k_wsplit(const float* __restrict__ W) {
    int i = blockIdx.x * blockDim.x + threadIdx.x;     // pair index
    if (i * 2 >= OUT_DIM * IN_DIM) return;
    float2 v = ((const float2*)W)[i];
    __nv_bfloat16 hx = __float2bfloat16(v.x), hy = __float2bfloat16(v.y);
    __nv_bfloat16 lx = __float2bfloat16(v.x - __bfloat162float(hx));
    __nv_bfloat16 ly = __float2bfloat16(v.y - __bfloat162float(hy));
    ((__nv_bfloat162*)g_whi)[i] = __halves2bfloat162(hx, hy);
    ((__nv_bfloat162*)g_wlo)[i] = __halves2bfloat162(lx, ly);
}

// ---------------------------------------------------------------- graph-norm build
__global__ void k_deg(const int* __restrict__ ei) {
    int e = (blockIdx.x * blockDim.x + threadIdx.x) * 2;   // E even
    if (e < E_EDGES) {
        int2 c2 = *(const int2*)(ei + E_EDGES + e);
        atomicAdd(&g_indeg[c2.x], 1);
        atomicAdd(&g_indeg[c2.y], 1);
    }
}
// single-block exclusive scan, 4 elems/thread (int4), fused dinv
__global__ void __launch_bounds__(1024) k_scan() {
    __shared__ int wsum[32];
    int lane = threadIdx.x & 31, wid = threadIdx.x >> 5;
    int carry = 0;
    for (int base = 0; base < N_NODES; base += 4096) {
        int i4 = base + threadIdx.x * 4;
        int4 v = make_int4(0, 0, 0, 0);
        if (i4 < N_NODES) v = *(const int4*)(g_indeg + i4);   // N%4==0: full or none
        int vs = v.x + v.y + v.z + v.w;
        int x = vs;
#pragma unroll
        for (int d = 1; d < 32; d <<= 1) {
            int y = __shfl_up_sync(0xFFFFFFFFu, x, d);
            if (lane >= d) x += y;
        }
        if (lane == 31) wsum[wid] = x;
        __syncthreads();
        if (wid == 0) {
            int w = wsum[lane];
#pragma unroll
            for (int d = 1; d < 32; d <<= 1) {
                int y = __shfl_up_sync(0xFFFFFFFFu, w, d);
                if (lane >= d) w += y;
            }
            wsum[lane] = w;
        }
        __syncthreads();
        int excl = x - vs + (wid > 0 ? wsum[wid - 1] : 0) + carry;
        if (i4 < N_NODES) {
            int e0 = excl;
            int e1 = e0 + v.x;
            int e2 = e1 + v.y;
            int e3 = e2 + v.z;
            g_off[i4] = e0;     g_cursor[i4] = e0;
            g_off[i4 + 1] = e1; g_cursor[i4 + 1] = e1;
            g_off[i4 + 2] = e2; g_cursor[i4 + 2] = e2;
            g_off[i4 + 3] = e3; g_cursor[i4 + 3] = e3;
            g_dinv[i4]     = rsqrtf((float)(v.x + 1));
            g_dinv[i4 + 1] = rsqrtf((float)(v.y + 1));
            g_dinv[i4 + 2] = rsqrtf((float)(v.z + 1));
            g_dinv[i4 + 3] = rsqrtf((float)(v.w + 1));
        }
        carry += wsum[31];
        __syncthreads();
    }
    if (threadIdx.x == 0) g_off[N_NODES] = E_EDGES;
}
__global__ void k_place(const int* __restrict__ ei) {
    int e = (blockIdx.x * blockDim.x + threadIdx.x) * 2;   // E even
    if (e < E_EDGES) {
        int2 r2 = *(const int2*)(ei + e);
        int2 c2 = *(const int2*)(ei + E_EDGES + e);
        float dr0 = g_dinv[r2.x], dc0 = g_dinv[c2.x];
        float dr1 = g_dinv[r2.y], dc1 = g_dinv[c2.y];
        int p0 = atomicAdd(&g_cursor[c2.x], 1);
        g_edge[p0] = make_uint2((uint32_t)r2.x, __float_as_uint(dr0 * dc0));
        int p1 = atomicAdd(&g_cursor[c2.y], 1);
        g_edge[p1] = make_uint2((uint32_t)r2.y, __float_as_uint(dr1 * dc1));
    }
}

// ---------------------------------------------------------------- HMMA GEMM (R8 form)
// h = normalize(x @ W^T + b) * SCALE via bf16 2-split (hi*hi + hi*lo + lo*hi).
// A (X) split in-register during staging; B (W) pre-split in global.
// CTA 128x128, 8 warps (32m x 64n), m16n8k16; 2 CTAs/SM.
// Epilogue also writes the fp16 mirror g_h16.
#define RS 40
__global__ void __launch_bounds__(256, 2) k_gemm_mma(const float* __restrict__ X,
                                                     const float* __restrict__ B) {
    __shared__ __nv_bfloat16 sAhi[128 * RS], sAlo[128 * RS];
    __shared__ __nv_bfloat16 sBhi[128 * RS], sBlo[128 * RS];
    __shared__ float s_bias[OUT_DIM];
    __shared__ float s_ssq[128][2];

    int tid = threadIdx.x, lane = tid & 31, wid = tid >> 5;
    int warp_m = wid & 3, warp_n = wid >> 2;
    int row0 = blockIdx.x * 128;
    if (tid < OUT_DIM) s_bias[tid] = B[tid];

    uint32_t aAhi = smem_u32(sAhi), aAlo = smem_u32(sAlo);
    uint32_t aBhi = smem_u32(sBhi), aBlo = smem_u32(sBlo);

    float c[2][8][4];
#pragma unroll
    for (int mi = 0; mi < 2; mi++)
#pragma unroll
        for (int nj = 0; nj < 8; nj++)
#pragma unroll
            for (int q = 0; q < 4; q++) c[mi][nj][q] = 0.f;

    uint32_t a_row = lane & 15;
    uint32_t a_kh  = lane >> 4;
    uint32_t b_g   = lane >> 3;
    uint32_t b_ln  = lane & 7;

    for (int step = 0; step < 8; step++) {
        int k0 = step * 32;
        for (int t = tid; t < 1024; t += 256) {
            int r  = t >> 3;
            int cc = (t & 7) << 2;
            int so = r * RS + cc;
            int gr = row0 + r;

            float4 xv = make_float4(0.f, 0.f, 0.f, 0.f);
            if (gr < N_NODES)
                xv = *(const float4*)(X + (size_t)gr * IN_DIM + k0 + cc);
            __nv_bfloat162 h01, h23, l01, l23;
            split2(xv.x, xv.y, h01, l01);
            split2(xv.z, xv.w, h23, l23);
            *(__nv_bfloat162*)(sAhi + so)     = h01;
            *(__nv_bfloat162*)(sAhi + so + 2) = h23;
            *(__nv_bfloat162*)(sAlo + so)     = l01;
            *(__nv_bfloat162*)(sAlo + so + 2) = l23;

            *(uint2*)(sBhi + so) = *(const uint2*)(g_whi + (size_t)r * IN_DIM + k0 + cc);
            *(uint2*)(sBlo + so) = *(const uint2*)(g_wlo + (size_t)r * IN_DIM + k0 + cc);
        }
        __syncthreads();

#pragma unroll
        for (int kk = 0; kk < 32; kk += 16) {
            uint32_t ah[2][4], al[2][4];
#pragma unroll
            for (int mi = 0; mi < 2; mi++) {
                uint32_t off = (uint32_t)(warp_m * 32 + mi * 16 + a_row) * (RS * 2)
                             + (kk + a_kh * 8) * 2;
                ldsm_x4(ah[mi], aAhi + off);
                ldsm_x4(al[mi], aAlo + off);
            }
#pragma unroll
            for (int njp = 0; njp < 4; njp++) {
                uint32_t row = (uint32_t)(warp_n * 64 + njp * 16 + (b_g >> 1) * 8 + b_ln);
                uint32_t off = row * (RS * 2) + (kk + (b_g & 1) * 8) * 2;
                uint32_t bh[4], bl[4];
                ldsm_x4(bh, aBhi + off);
                ldsm_x4(bl, aBlo + off);
#pragma unroll
                for (int mi = 0; mi < 2; mi++) {
                    mma_bf16(c[mi][njp * 2],     ah[mi], bh);
                    mma_bf16(c[mi][njp * 2],     ah[mi], bl);
                    mma_bf16(c[mi][njp * 2],     al[mi], bh);
                    mma_bf16(c[mi][njp * 2 + 1], ah[mi], bh + 2);
                    mma_bf16(c[mi][njp * 2 + 1], ah[mi], bl + 2);
                    mma_bf16(c[mi][njp * 2 + 1], al[mi], bh + 2);
                }
            }
        }
        __syncthreads();
    }

    int qr = lane >> 2;
    int qc = (lane & 3) * 2;
    float sq[2][2] = {{0.f, 0.f}, {0.f, 0.f}};
#pragma unroll
    for (int mi = 0; mi < 2; mi++)
#pragma unroll
        for (int nj = 0; nj < 8; nj++) {
            int colb = warp_n * 64 + nj * 8 + qc;
            float b0 = s_bias[colb], b1 = s_bias[colb + 1];
            c[mi][nj][0] += b0; c[mi][nj][1] += b1;
            c[mi][nj][2] += b0; c[mi][nj][3] += b1;
            sq[mi][0] += c[mi][nj][0] * c[mi][nj][0] + c[mi][nj][1] * c[mi][nj][1];
            sq[mi][1] += c[mi][nj][2] * c[mi][nj][2] + c[mi][nj][3] * c[mi][nj][3];
        }
#pragma unroll
    for (int mi = 0; mi < 2; mi++)
#pragma unroll
        for (int h = 0; h < 2; h++) {
            float v = sq[mi][h];
            v += __shfl_xor_sync(0xFFFFFFFFu, v, 1);
            v += __shfl_xor_sync(0xFFFFFFFFu, v, 2);
            if ((lane & 3) == 0)
                s_ssq[warp_m * 32 + mi * 16 + h * 8 + qr][warp_n] = v;
        }
    __syncthreads();
#pragma unroll
    for (int mi = 0; mi < 2; mi++)
#pragma unroll
        for (int h = 0; h < 2; h++) {
            int rloc = warp_m * 32 + mi * 16 + h * 8 + qr;
            float tot = s_ssq[rloc][0] + s_ssq[rloc][1];
            float s = SCALE / fmaxf(sqrtf(tot), 1e-12f);
            int gr = row0 + rloc;
            if (gr < N_NODES) {
                float*  o  = g_h   + (size_t)gr * OUT_DIM + warp_n * 64 + qc;
                __half* o16 = g_h16 + (size_t)gr * OUT_DIM + warp_n * 64 + qc;
#pragma unroll
                for (int nj = 0; nj < 8; nj++) {
                    float2 w2;
                    w2.x = c[mi][nj][h * 2] * s;
                    w2.y = c[mi][nj][h * 2 + 1] * s;
                    *(float2*)(o + nj * 8) = w2;
                    *(__half2*)(o16 + nj * 8) = __floats2half2_rn(w2.x, w2.y);
                }
            }
        }
}

// ---------------------------------------------------------------- gather rounds
// neighbors read from fp16 mirrors; self/teleport rows in fp32; fp32 accumulate.
__global__ void __launch_bounds__(256) k_gather1() {
    int n = blockIdx.x * 8 + (threadIdx.x >> 5);
    int lane = threadIdx.x & 31;
    if (n >= N_NODES) return;

    int e0 = g_off[n], e1 = g_off[n + 1];
    float4 acc = make_float4(0.f, 0.f, 0.f, 0.f);
#pragma unroll 2
    for (int e = e0; e < e1; e++) {
        uint2 ed = g_edge[e];
        float w = __uint_as_float(ed.y);
        uint2 pk = __ldg((const uint2*)(g_h16 + (size_t)ed.x * OUT_DIM) + lane);
        acc_h4(acc, w, pk);
    }
    float dn = g_dinv[n];
    float sc = ONE_MA * dn * dn + ALPHA;
    float4 hh = __ldg((const float4*)(g_h + (size_t)n * OUT_DIM) + lane);
    float4 o;
    o.x = ONE_MA * acc.x + sc * hh.x;
    o.y = ONE_MA * acc.y + sc * hh.y;
    o.z = ONE_MA * acc.z + sc * hh.z;
    o.w = ONE_MA * acc.w + sc * hh.w;
    *((float4*)(g_z + (size_t)n * OUT_DIM) + lane) = o;
    uint2 zp;
    *reinterpret_cast<__half2*>(&zp.x) = __floats2half2_rn(o.x, o.y);
    *reinterpret_cast<__half2*>(&zp.y) = __floats2half2_rn(o.z, o.w);
    *((uint2*)(g_z16 + (size_t)n * OUT_DIM) + lane) = zp;
}

__global__ void __launch_bounds__(256) k_gather2(float* __restrict__ out) {
    int n = blockIdx.x * 8 + (threadIdx.x >> 5);
    int lane = threadIdx.x & 31;
    if (n >= N_NODES) return;

    int e0 = g_off[n], e1 = g_off[n + 1];
    float4 acc = make_float4(0.f, 0.f, 0.f, 0.f);
#pragma unroll 2
    for (int e = e0; e < e1; e++) {
        uint2 ed = g_edge[e];
        float w = __uint_as_float(ed.y);
        uint2 pk = __ldg((const uint2*)(g_z16 + (size_t)ed.x * OUT_DIM) + lane);
        acc_h4(acc, w, pk);
    }
    float dn = g_dinv[n];
    float sw = dn * dn;
    float4 cur = __ldg((const float4*)(g_z + (size_t)n * OUT_DIM) + lane);
    float4 hh  = __ldg((const float4*)(g_h + (size_t)n * OUT_DIM) + lane);
    float4 o;
    o.x = ONE_MA * (acc.x + sw * cur.x) + ALPHA * hh.x;
    o.y = ONE_MA * (acc.y + sw * cur.y) + ALPHA * hh.y;
    o.z = ONE_MA * (acc.z + sw * cur.z) + ALPHA * hh.z;
    o.w = ONE_MA * (acc.w + sw * cur.w) + ALPHA * hh.w;
    *((float4*)(out + (size_t)n * OUT_DIM) + lane) = o;
}

// ----------------------------------------------------------------
extern "C" void kernel_launch(void* const* d_in, const int* in_sizes, int n_in,
                              void* d_out, int out_size) {
    const float* x  = (const float*)d_in[0];
    const int*   ei = (const int*)d_in[1];
    const float* W  = (const float*)d_in[2];
    const float* b  = (const float*)d_in[3];
    float* out = (float*)d_out;

    // one-time side-stream + events + symbol address (host resources only)
    static cudaStream_t s2 = nullptr;
    static cudaEvent_t ev_fork = nullptr, ev_join = nullptr;
    static void* indeg_ptr = nullptr;
    if (s2 == nullptr) {
        cudaStreamCreateWithFlags(&s2, cudaStreamNonBlocking);
        cudaEventCreateWithFlags(&ev_fork, cudaEventDisableTiming);
        cudaEventCreateWithFlags(&ev_join, cudaEventDisableTiming);
        cudaGetSymbolAddress(&indeg_ptr, g_indeg);
    }

    // fork: CSR build on s2; W-split + GEMM on the main (capture) stream
    cudaEventRecord(ev_fork, 0);
    cudaStreamWaitEvent(s2, ev_fork, 0);

    cudaMemsetAsync(indeg_ptr, 0, N_NODES * sizeof(int), s2);
    k_deg  <<<(E_EDGES / 2 + 255) / 256, 256, 0, s2>>>(ei);
    k_scan <<<1, 1024, 0, s2>>>();
    k_place<<<(E_EDGES / 2 + 255) / 256, 256, 0, s2>>>(ei);
    cudaEventRecord(ev_join, s2);

    k_wsplit<<<(OUT_DIM * IN_DIM / 2 + 255) / 256, 256>>>(W);
    k_gemm_mma<<<(N_NODES + 127) / 128, 256>>>(x, b);

    // join: gathers need both the GEMM (g_h/g_h16) and the CSR build
    cudaStreamWaitEvent(0, ev_join, 0);
    k_gather1<<<(N_NODES + 7) / 8, 256>>>();
    k_gather2<<<(N_NODES + 7) / 8, 256>>>(out);
}

// round 11
// speedup vs baseline: 1.1674x; 1.0991x over previous
#include <cuda_runtime.h>
#include <cuda_bf16.h>
#include <cstdint>

#define N_NODES 50000
#define E_EDGES 600000
#define IN_DIM  256
#define OUT_DIM 128
#define SCALE   1.8f
#define ALPHA   0.15f
#define ONE_MA  0.85f

// ---------------------------------------------------------------- scratch
__device__ float g_h[(size_t)N_NODES * OUT_DIM];
__device__ float g_z[(size_t)N_NODES * OUT_DIM];
__device__ __align__(16) int g_indeg[N_NODES];
__device__ int   g_off[N_NODES + 1];
__device__ int   g_cursor[N_NODES];
__device__ float g_dinv[N_NODES];
__device__ uint2 g_edge[E_EDGES];          // packed (src, weight)
__device__ __nv_bfloat16 g_whi[(size_t)OUT_DIM * IN_DIM];
__device__ __nv_bfloat16 g_wlo[(size_t)OUT_DIM * IN_DIM];

// ---------------------------------------------------------------- helpers
__device__ __forceinline__ uint32_t smem_u32(const void* p) {
    uint32_t a;
    asm("{ .reg .u64 t; cvta.to.shared.u64 t, %1; cvt.u32.u64 %0, t; }" : "=r"(a) : "l"(p));
    return a;
}
__device__ __forceinline__ void ldsm_x4(uint32_t* r, uint32_t addr) {
    asm volatile("ldmatrix.sync.aligned.m8n8.x4.shared.b16 {%0,%1,%2,%3}, [%4];"
                 : "=r"(r[0]), "=r"(r[1]), "=r"(r[2]), "=r"(r[3]) : "r"(addr));
}
__device__ __forceinline__ void mma_bf16(float* c, const uint32_t* a, const uint32_t* b) {
    asm volatile("mma.sync.aligned.m16n8k16.row.col.f32.bf16.bf16.f32 "
                 "{%0,%1,%2,%3}, {%4,%5,%6,%7}, {%8,%9}, {%0,%1,%2,%3};"
                 : "+f"(c[0]), "+f"(c[1]), "+f"(c[2]), "+f"(c[3])
                 : "r"(a[0]), "r"(a[1]), "r"(a[2]), "r"(a[3]), "r"(b[0]), "r"(b[1]));
}
__device__ __forceinline__ void split2(float x, float y,
                                       __nv_bfloat162& hi, __nv_bfloat162& lo) {
    __nv_bfloat16 hx = __float2bfloat16(x), hy = __float2bfloat16(y);
    __nv_bfloat16 lx = __float2bfloat16(x - __bfloat162float(hx));
    __nv_bfloat16 ly = __float2bfloat16(y - __bfloat162float(hy));
    hi = __halves2bfloat162(hx, hy);
    lo = __halves2bfloat162(lx, ly);
}

// ---------------------------------------------------------------- W pre-split
__global__ void k_wsplit(const float* __restrict__ W) {
    int i = blockIdx.x * blockDim.x + threadIdx.x;     // pair index
    if (i * 2 >= OUT_DIM * IN_DIM) return;
    float2 v = ((const float2*)W)[i];
    __nv_bfloat16 hx = __float2bfloat16(v.x), hy = __float2bfloat16(v.y);
    __nv_bfloat16 lx = __float2bfloat16(v.x - __bfloat162float(hx));
    __nv_bfloat16 ly = __float2bfloat16(v.y - __bfloat162float(hy));
    ((__nv_bfloat162*)g_whi)[i] = __halves2bfloat162(hx, hy);
    ((__nv_bfloat162*)g_wlo)[i] = __halves2bfloat162(lx, ly);
}

// ---------------------------------------------------------------- graph-norm build
__global__ void k_deg(const int* __restrict__ ei) {
    int e = (blockIdx.x * blockDim.x + threadIdx.x) * 2;   // E even
    if (e < E_EDGES) {
        int2 c2 = *(const int2*)(ei + E_EDGES + e);
        atomicAdd(&g_indeg[c2.x], 1);
        atomicAdd(&g_indeg[c2.y], 1);
    }
}
// single-block exclusive scan, 4 elems/thread (int4), fused dinv
__global__ void __launch_bounds__(1024) k_scan() {
    __shared__ int wsum[32];
    int lane = threadIdx.x & 31, wid = threadIdx.x >> 5;
    int carry = 0;
    for (int base = 0; base < N_NODES; base += 4096) {
        int i4 = base + threadIdx.x * 4;
        int4 v = make_int4(0, 0, 0, 0);
        if (i4 < N_NODES) v = *(const int4*)(g_indeg + i4);   // N%4==0: full or none
        int vs = v.x + v.y + v.z + v.w;
        int x = vs;
#pragma unroll
        for (int d = 1; d < 32; d <<= 1) {
            int y = __shfl_up_sync(0xFFFFFFFFu, x, d);
            if (lane >= d) x += y;
        }
        if (lane == 31) wsum[wid] = x;
        __syncthreads();
        if (wid == 0) {
            int w = wsum[lane];
#pragma unroll
            for (int d = 1; d < 32; d <<= 1) {
                int y = __shfl_up_sync(0xFFFFFFFFu, w, d);
                if (lane >= d) w += y;
            }
            wsum[lane] = w;
        }
        __syncthreads();
        int excl = x - vs + (wid > 0 ? wsum[wid - 1] : 0) + carry;
        if (i4 < N_NODES) {
            int e0 = excl;
            int e1 = e0 + v.x;
            int e2 = e1 + v.y;
            int e3 = e2 + v.z;
            g_off[i4] = e0;     g_cursor[i4] = e0;
            g_off[i4 + 1] = e1; g_cursor[i4 + 1] = e1;
            g_off[i4 + 2] = e2; g_cursor[i4 + 2] = e2;
            g_off[i4 + 3] = e3; g_cursor[i4 + 3] = e3;
            g_dinv[i4]     = rsqrtf((float)(v.x + 1));
            g_dinv[i4 + 1] = rsqrtf((float)(v.y + 1));
            g_dinv[i4 + 2] = rsqrtf((float)(v.z + 1));
            g_dinv[i4 + 3] = rsqrtf((float)(v.w + 1));
        }
        carry += wsum[31];
        __syncthreads();
    }
    if (threadIdx.x == 0) g_off[N_NODES] = E_EDGES;
}
__global__ void k_place(const int* __restrict__ ei) {
    int e = (blockIdx.x * blockDim.x + threadIdx.x) * 2;   // E even
    if (e < E_EDGES) {
        int2 r2 = *(const int2*)(ei + e);
        int2 c2 = *(const int2*)(ei + E_EDGES + e);
        float dr0 = g_dinv[r2.x], dc0 = g_dinv[c2.x];
        float dr1 = g_dinv[r2.y], dc1 = g_dinv[c2.y];
        int p0 = atomicAdd(&g_cursor[c2.x], 1);
        g_edge[p0] = make_uint2((uint32_t)r2.x, __float_as_uint(dr0 * dc0));
        int p1 = atomicAdd(&g_cursor[c2.y], 1);
        g_edge[p1] = make_uint2((uint32_t)r2.y, __float_as_uint(dr1 * dc1));
    }
}

// ---------------------------------------------------------------- HMMA GEMM
// h = normalize(x @ W^T + b) * SCALE via bf16 2-split (hi*hi + hi*lo + lo*hi).
// 64-row CTA tile (grid 782) for small wave-quantization tail; 3 CTAs/SM.
// 8 warps: warp = 32m x 32n, m16n8k16. B (W) pre-split in global.
#define RS 40
__global__ void __launch_bounds__(256, 3) k_gemm_mma(const float* __restrict__ X,
                                                     const float* __restrict__ B) {
    __shared__ __nv_bfloat16 sAhi[64 * RS], sAlo[64 * RS];
    __shared__ __nv_bfloat16 sBhi[128 * RS], sBlo[128 * RS];
    __shared__ float s_bias[OUT_DIM];
    __shared__ float s_ssq[64][4];

    int tid = threadIdx.x, lane = tid & 31, wid = tid >> 5;
    int warp_m = wid & 1;          // 0..1  (32 rows each)
    int warp_n = wid >> 1;         // 0..3  (32 cols each)
    int row0 = blockIdx.x * 64;
    if (tid < OUT_DIM) s_bias[tid] = B[tid];

    uint32_t aAhi = smem_u32(sAhi), aAlo = smem_u32(sAlo);
    uint32_t aBhi = smem_u32(sBhi), aBlo = smem_u32(sBlo);

    float c[2][4][4];
#pragma unroll
    for (int mi = 0; mi < 2; mi++)
#pragma unroll
        for (int nj = 0; nj < 4; nj++)
#pragma unroll
            for (int q = 0; q < 4; q++) c[mi][nj][q] = 0.f;

    uint32_t a_row = lane & 15;
    uint32_t a_kh  = lane >> 4;
    uint32_t b_g   = lane >> 3;
    uint32_t b_ln  = lane & 7;

    for (int step = 0; step < 8; step++) {
        int k0 = step * 32;
        // stage X: 64 rows x 32 k (fp32 -> bf16 hi/lo in-register)
        for (int t = tid; t < 512; t += 256) {
            int r  = t >> 3;
            int cc = (t & 7) << 2;
            int so = r * RS + cc;
            int gr = row0 + r;
            float4 xv = make_float4(0.f, 0.f, 0.f, 0.f);
            if (gr < N_NODES)
                xv = *(const float4*)(X + (size_t)gr * IN_DIM + k0 + cc);
            __nv_bfloat162 h01, h23, l01, l23;
            split2(xv.x, xv.y, h01, l01);
            split2(xv.z, xv.w, h23, l23);
            *(__nv_bfloat162*)(sAhi + so)     = h01;
            *(__nv_bfloat162*)(sAhi + so + 2) = h23;
            *(__nv_bfloat162*)(sAlo + so)     = l01;
            *(__nv_bfloat162*)(sAlo + so + 2) = l23;
        }
        // stage W: 128 rows x 32 k (pre-split, pure copy)
        for (int t = tid; t < 1024; t += 256) {
            int r  = t >> 3;
            int cc = (t & 7) << 2;
            int so = r * RS + cc;
            *(uint2*)(sBhi + so) = *(const uint2*)(g_whi + (size_t)r * IN_DIM + k0 + cc);
            *(uint2*)(sBlo + so) = *(const uint2*)(g_wlo + (size_t)r * IN_DIM + k0 + cc);
        }
        __syncthreads();

#pragma unroll
        for (int kk = 0; kk < 32; kk += 16) {
            uint32_t ah[2][4], al[2][4];
#pragma unroll
            for (int mi = 0; mi < 2; mi++) {
                uint32_t off = (uint32_t)(warp_m * 32 + mi * 16 + a_row) * (RS * 2)
                             + (kk + a_kh * 8) * 2;
                ldsm_x4(ah[mi], aAhi + off);
                ldsm_x4(al[mi], aAlo + off);
            }
#pragma unroll
            for (int njp = 0; njp < 2; njp++) {
                uint32_t row = (uint32_t)(warp_n * 32 + njp * 16 + (b_g >> 1) * 8 + b_ln);
                uint32_t off = row * (RS * 2) + (kk + (b_g & 1) * 8) * 2;
                uint32_t bh[4], bl[4];
                ldsm_x4(bh, aBhi + off);
                ldsm_x4(bl, aBlo + off);
#pragma unroll
                for (int mi = 0; mi < 2; mi++) {
                    mma_bf16(c[mi][njp * 2],     ah[mi], bh);
                    mma_bf16(c[mi][njp * 2],     ah[mi], bl);
                    mma_bf16(c[mi][njp * 2],     al[mi], bh);
                    mma_bf16(c[mi][njp * 2 + 1], ah[mi], bh + 2);
                    mma_bf16(c[mi][njp * 2 + 1], ah[mi], bl + 2);
                    mma_bf16(c[mi][njp * 2 + 1], al[mi], bh + 2);
                }
            }
        }
        __syncthreads();
    }

    // epilogue: bias, row L2-norm across four warp_n quarters, scale, store
    int qr = lane >> 2;
    int qc = (lane & 3) * 2;
    float sq[2][2] = {{0.f, 0.f}, {0.f, 0.f}};
#pragma unroll
    for (int mi = 0; mi < 2; mi++)
#pragma unroll
        for (int nj = 0; nj < 4; nj++) {
            int colb = warp_n * 32 + nj * 8 + qc;
            float b0 = s_bias[colb], b1 = s_bias[colb + 1];
            c[mi][nj][0] += b0; c[mi][nj][1] += b1;
            c[mi][nj][2] += b0; c[mi][nj][3] += b1;
            sq[mi][0] += c[mi][nj][0] * c[mi][nj][0] + c[mi][nj][1] * c[mi][nj][1];
            sq[mi][1] += c[mi][nj][2] * c[mi][nj][2] + c[mi][nj][3] * c[mi][nj][3];
        }
#pragma unroll
    for (int mi = 0; mi < 2; mi++)
#pragma unroll
        for (int h = 0; h < 2; h++) {
            float v = sq[mi][h];
            v += __shfl_xor_sync(0xFFFFFFFFu, v, 1);
            v += __shfl_xor_sync(0xFFFFFFFFu, v, 2);
            if ((lane & 3) == 0)
                s_ssq[warp_m * 32 + mi * 16 + h * 8 + qr][warp_n] = v;
        }
    __syncthreads();
#pragma unroll
    for (int mi = 0; mi < 2; mi++)
#pragma unroll
        for (int h = 0; h < 2; h++) {
            int rloc = warp_m * 32 + mi * 16 + h * 8 + qr;
            float tot = s_ssq[rloc][0] + s_ssq[rloc][1] + s_ssq[rloc][2] + s_ssq[rloc][3];
            float s = SCALE / fmaxf(sqrtf(tot), 1e-12f);
            int gr = row0 + rloc;
            if (gr < N_NODES) {
                float* o = g_h + (size_t)gr * OUT_DIM + warp_n * 32 + qc;
#pragma unroll
                for (int nj = 0; nj < 4; nj++) {
                    float2 w2;
                    w2.x = c[mi][nj][h * 2] * s;
                    w2.y = c[mi][nj][h * 2 + 1] * s;
                    *(float2*)(o + nj * 8) = w2;
                }
            }
        }
}

// ---------------------------------------------------------------- gather rounds (R8/R6 form)
__global__ void __launch_bounds__(256) k_gather1() {
    int n = blockIdx.x * 8 + (threadIdx.x >> 5);
    int lane = threadIdx.x & 31;
    if (n >= N_NODES) return;

    int e0 = g_off[n], e1 = g_off[n + 1];
    float4 acc = make_float4(0.f, 0.f, 0.f, 0.f);
#pragma unroll 2
    for (int e = e0; e < e1; e++) {
        uint2 ed = g_edge[e];
        float w = __uint_as_float(ed.y);
        float4 v = __ldg((const float4*)(g_h + (size_t)ed.x * OUT_DIM) + lane);
        acc.x += w * v.x; acc.y += w * v.y; acc.z += w * v.z; acc.w += w * v.w;
    }
    float dn = g_dinv[n];
    float sc = ONE_MA * dn * dn + ALPHA;
    float4 hh = __ldg((const float4*)(g_h + (size_t)n * OUT_DIM) + lane);
    float4 o;
    o.x = ONE_MA * acc.x + sc * hh.x;
    o.y = ONE_MA * acc.y + sc * hh.y;
    o.z = ONE_MA * acc.z + sc * hh.z;
    o.w = ONE_MA * acc.w + sc * hh.w;
    *((float4*)(g_z + (size_t)n * OUT_DIM) + lane) = o;
}

__global__ void __launch_bounds__(256) k_gather2(float* __restrict__ out) {
    int n = blockIdx.x * 8 + (threadIdx.x >> 5);
    int lane = threadIdx.x & 31;
    if (n >= N_NODES) return;

    int e0 = g_off[n], e1 = g_off[n + 1];
    float4 acc = make_float4(0.f, 0.f, 0.f, 0.f);
#pragma unroll 2
    for (int e = e0; e < e1; e++) {
        uint2 ed = g_edge[e];
        float w = __uint_as_float(ed.y);
        float4 v = __ldg((const float4*)(g_z + (size_t)ed.x * OUT_DIM) + lane);
        acc.x += w * v.x; acc.y += w * v.y; acc.z += w * v.z; acc.w += w * v.w;
    }
    float dn = g_dinv[n];
    float sw = dn * dn;
    float4 cur = __ldg((const float4*)(g_z + (size_t)n * OUT_DIM) + lane);
    float4 hh  = __ldg((const float4*)(g_h + (size_t)n * OUT_DIM) + lane);
    float4 o;
    o.x = ONE_MA * (acc.x + sw * cur.x) + ALPHA * hh.x;
    o.y = ONE_MA * (acc.y + sw * cur.y) + ALPHA * hh.y;
    o.z = ONE_MA * (acc.z + sw * cur.z) + ALPHA * hh.z;
    o.w = ONE_MA * (acc.w + sw * cur.w) + ALPHA * hh.w;
    *((float4*)(out + (size_t)n * OUT_DIM) + lane) = o;
}

// ----------------------------------------------------------------
extern "C" void kernel_launch(void* const* d_in, const int* in_sizes, int n_in,
                              void* d_out, int out_size) {
    const float* x  = (const float*)d_in[0];
    const int*   ei = (const int*)d_in[1];
    const float* W  = (const float*)d_in[2];
    const float* b  = (const float*)d_in[3];
    float* out = (float*)d_out;

    // one-time side-stream + events + symbol address (host resources only)
    static cudaStream_t s2 = nullptr;
    static cudaEvent_t ev_fork = nullptr, ev_join = nullptr;
    static void* indeg_ptr = nullptr;
    if (s2 == nullptr) {
        cudaStreamCreateWithFlags(&s2, cudaStreamNonBlocking);
        cudaEventCreateWithFlags(&ev_fork, cudaEventDisableTiming);
        cudaEventCreateWithFlags(&ev_join, cudaEventDisableTiming);
        cudaGetSymbolAddress(&indeg_ptr, g_indeg);
    }

    // fork: CSR build on s2; W-split + GEMM on the main (capture) stream
    cudaEventRecord(ev_fork, 0);
    cudaStreamWaitEvent(s2, ev_fork, 0);

    cudaMemsetAsync(indeg_ptr, 0, N_NODES * sizeof(int), s2);
    k_deg  <<<(E_EDGES / 2 + 255) / 256, 256, 0, s2>>>(ei);
    k_scan <<<1, 1024, 0, s2>>>();
    k_place<<<(E_EDGES / 2 + 255) / 256, 256, 0, s2>>>(ei);
    cudaEventRecord(ev_join, s2);

    k_wsplit<<<(OUT_DIM * IN_DIM / 2 + 255) / 256, 256>>>(W);
    k_gemm_mma<<<(N_NODES + 63) / 64, 256>>>(x, b);

    // join: gathers need both the GEMM (g_h) and the CSR build
    cudaStreamWaitEvent(0, ev_join, 0);
    k_gather1<<<(N_NODES + 7) / 8, 256>>>();
    k_gather2<<<(N_NODES + 7) / 8, 256>>>(out);
}

// round 12
// speedup vs baseline: 1.2219x; 1.0467x over previous
#include <cuda_runtime.h>
#include <cuda_fp16.h>
#include <cstdint>

#define N_NODES 50000
#define E_EDGES 600000
#define IN_DIM  256
#define OUT_DIM 128
#define SCALE   1.8f
#define ALPHA   0.15f
#define ONE_MA  0.85f

// ---------------------------------------------------------------- scratch
__device__ float g_h[(size_t)N_NODES * OUT_DIM];
__device__ float g_z[(size_t)N_NODES * OUT_DIM];
__device__ __align__(16) int g_indeg[N_NODES];
__device__ int   g_off[N_NODES + 1];
__device__ int   g_cursor[N_NODES];
__device__ float g_dinv[N_NODES];
__device__ uint2 g_edge[E_EDGES];          // packed (src, weight)
__device__ __half g_wh[(size_t)OUT_DIM * IN_DIM];   // W in fp16

// ---------------------------------------------------------------- helpers
__device__ __forceinline__ uint32_t smem_u32(const void* p) {
    uint32_t a;
    asm("{ .reg .u64 t; cvta.to.shared.u64 t, %1; cvt.u32.u64 %0, t; }" : "=r"(a) : "l"(p));
    return a;
}
__device__ __forceinline__ void ldsm_x4(uint32_t* r, uint32_t addr) {
    asm volatile("ldmatrix.sync.aligned.m8n8.x4.shared.b16 {%0,%1,%2,%3}, [%4];"
                 : "=r"(r[0]), "=r"(r[1]), "=r"(r[2]), "=r"(r[3]) : "r"(addr));
}
__device__ __forceinline__ void mma_fp16(float* c, const uint32_t* a, const uint32_t* b) {
    asm volatile("mma.sync.aligned.m16n8k16.row.col.f32.f16.f16.f32 "
                 "{%0,%1,%2,%3}, {%4,%5,%6,%7}, {%8,%9}, {%0,%1,%2,%3};"
                 : "+f"(c[0]), "+f"(c[1]), "+f"(c[2]), "+f"(c[3])
                 : "r"(a[0]), "r"(a[1]), "r"(a[2]), "r"(a[3]), "r"(b[0]), "r"(b[1]));
}
// fp16 two-term split: hi + lo reconstructs x to ~2^-22
__device__ __forceinline__ void split2h(float x, float y, __half2& hi, __half2& lo) {
    __half hx = __float2half_rn(x), hy = __float2half_rn(y);
    __half lx = __float2half_rn(x - __half2float(hx));
    __half ly = __float2half_rn(y - __half2float(hy));
    hi = __halves2half2(hx, hy);
    lo = __halves2half2(lx, ly);
}

// ---------------------------------------------------------------- W fp16 convert
__global__ void k_wconv(const float* __restrict__ W) {
    int i = blockIdx.x * blockDim.x + threadIdx.x;     // pair index
    if (i * 2 >= OUT_DIM * IN_DIM) return;
    float2 v = ((const float2*)W)[i];
    ((__half2*)g_wh)[i] = __floats2half2_rn(v.x, v.y);
}

// ---------------------------------------------------------------- graph-norm build
__global__ void k_deg(const int* __restrict__ ei) {
    int e = (blockIdx.x * blockDim.x + threadIdx.x) * 2;   // E even
    if (e < E_EDGES) {
        int2 c2 = *(const int2*)(ei + E_EDGES + e);
        atomicAdd(&g_indeg[c2.x], 1);
        atomicAdd(&g_indeg[c2.y], 1);
    }
}
// single-block exclusive scan, 4 elems/thread (int4), fused dinv
__global__ void __launch_bounds__(1024) k_scan() {
    __shared__ int wsum[32];
    int lane = threadIdx.x & 31, wid = threadIdx.x >> 5;
    int carry = 0;
    for (int base = 0; base < N_NODES; base += 4096) {
        int i4 = base + threadIdx.x * 4;
        int4 v = make_int4(0, 0, 0, 0);
        if (i4 < N_NODES) v = *(const int4*)(g_indeg + i4);   // N%4==0: full or none
        int vs = v.x + v.y + v.z + v.w;
        int x = vs;
#pragma unroll
        for (int d = 1; d < 32; d <<= 1) {
            int y = __shfl_up_sync(0xFFFFFFFFu, x, d);
            if (lane >= d) x += y;
        }
        if (lane == 31) wsum[wid] = x;
        __syncthreads();
        if (wid == 0) {
            int w = wsum[lane];
#pragma unroll
            for (int d = 1; d < 32; d <<= 1) {
                int y = __shfl_up_sync(0xFFFFFFFFu, w, d);
                if (lane >= d) w += y;
            }
            wsum[lane] = w;
        }
        __syncthreads();
        int excl = x - vs + (wid > 0 ? wsum[wid - 1] : 0) + carry;
        if (i4 < N_NODES) {
            int e0 = excl;
            int e1 = e0 + v.x;
            int e2 = e1 + v.y;
            int e3 = e2 + v.z;
            g_off[i4] = e0;     g_cursor[i4] = e0;
            g_off[i4 + 1] = e1; g_cursor[i4 + 1] = e1;
            g_off[i4 + 2] = e2; g_cursor[i4 + 2] = e2;
            g_off[i4 + 3] = e3; g_cursor[i4 + 3] = e3;
            g_dinv[i4]     = rsqrtf((float)(v.x + 1));
            g_dinv[i4 + 1] = rsqrtf((float)(v.y + 1));
            g_dinv[i4 + 2] = rsqrtf((float)(v.z + 1));
            g_dinv[i4 + 3] = rsqrtf((float)(v.w + 1));
        }
        carry += wsum[31];
        __syncthreads();
    }
    if (threadIdx.x == 0) g_off[N_NODES] = E_EDGES;
}
__global__ void k_place(const int* __restrict__ ei) {
    int e = (blockIdx.x * blockDim.x + threadIdx.x) * 2;   // E even
    if (e < E_EDGES) {
        int2 r2 = *(const int2*)(ei + e);
        int2 c2 = *(const int2*)(ei + E_EDGES + e);
        float dr0 = g_dinv[r2.x], dc0 = g_dinv[c2.x];
        float dr1 = g_dinv[r2.y], dc1 = g_dinv[c2.y];
        int p0 = atomicAdd(&g_cursor[c2.x], 1);
        g_edge[p0] = make_uint2((uint32_t)r2.x, __float_as_uint(dr0 * dc0));
        int p1 = atomicAdd(&g_cursor[c2.y], 1);
        g_edge[p1] = make_uint2((uint32_t)r2.y, __float_as_uint(dr1 * dc1));
    }
}

// ---------------------------------------------------------------- HMMA GEMM
// h = normalize(x @ W^T + b) * SCALE via fp16 2-product: (Ahi + Alo) * B,
// A = X split into fp16 hi/lo (exact to ~2^-22), B = W in fp16 (err ~2^-12).
// 64-row CTA tile (grid 782), 8 warps (32m x 32n), m16n8k16; 3 CTAs/SM.
#define RS 40
__global__ void __launch_bounds__(256, 3) k_gemm_mma(const float* __restrict__ X,
                                                     const float* __restrict__ B) {
    __shared__ __half sAhi[64 * RS], sAlo[64 * RS];
    __shared__ __half sB[128 * RS];
    __shared__ float s_bias[OUT_DIM];
    __shared__ float s_ssq[64][4];

    int tid = threadIdx.x, lane = tid & 31, wid = tid >> 5;
    int warp_m = wid & 1;          // 0..1  (32 rows each)
    int warp_n = wid >> 1;         // 0..3  (32 cols each)
    int row0 = blockIdx.x * 64;
    if (tid < OUT_DIM) s_bias[tid] = B[tid];

    uint32_t aAhi = smem_u32(sAhi), aAlo = smem_u32(sAlo);
    uint32_t aB = smem_u32(sB);

    float c[2][4][4];
#pragma unroll
    for (int mi = 0; mi < 2; mi++)
#pragma unroll
        for (int nj = 0; nj < 4; nj++)
#pragma unroll
            for (int q = 0; q < 4; q++) c[mi][nj][q] = 0.f;

    uint32_t a_row = lane & 15;
    uint32_t a_kh  = lane >> 4;
    uint32_t b_g   = lane >> 3;
    uint32_t b_ln  = lane & 7;

    for (int step = 0; step < 8; step++) {
        int k0 = step * 32;
        // stage X: 64 rows x 32 k (fp32 -> fp16 hi/lo in-register)
        for (int t = tid; t < 512; t += 256) {
            int r  = t >> 3;
            int cc = (t & 7) << 2;
            int so = r * RS + cc;
            int gr = row0 + r;
            float4 xv = make_float4(0.f, 0.f, 0.f, 0.f);
            if (gr < N_NODES)
                xv = *(const float4*)(X + (size_t)gr * IN_DIM + k0 + cc);
            __half2 h01, h23, l01, l23;
            split2h(xv.x, xv.y, h01, l01);
            split2h(xv.z, xv.w, h23, l23);
            *(__half2*)(sAhi + so)     = h01;
            *(__half2*)(sAhi + so + 2) = h23;
            *(__half2*)(sAlo + so)     = l01;
            *(__half2*)(sAlo + so + 2) = l23;
        }
        // stage W: 128 rows x 32 k (fp16, pure copy, 16B per thread-iter)
        for (int t = tid; t < 512; t += 256) {
            int r  = t >> 2;
            int cc = (t & 3) << 3;
            *(uint4*)(sB + r * RS + cc) =
                *(const uint4*)(g_wh + (size_t)r * IN_DIM + k0 + cc);
        }
        __syncthreads();

#pragma unroll
        for (int kk = 0; kk < 32; kk += 16) {
            uint32_t ah[2][4], al[2][4];
#pragma unroll
            for (int mi = 0; mi < 2; mi++) {
                uint32_t off = (uint32_t)(warp_m * 32 + mi * 16 + a_row) * (RS * 2)
                             + (kk + a_kh * 8) * 2;
                ldsm_x4(ah[mi], aAhi + off);
                ldsm_x4(al[mi], aAlo + off);
            }
#pragma unroll
            for (int njp = 0; njp < 2; njp++) {
                uint32_t row = (uint32_t)(warp_n * 32 + njp * 16 + (b_g >> 1) * 8 + b_ln);
                uint32_t off = row * (RS * 2) + (kk + (b_g & 1) * 8) * 2;
                uint32_t bh[4];
                ldsm_x4(bh, aB + off);
#pragma unroll
                for (int mi = 0; mi < 2; mi++) {
                    mma_fp16(c[mi][njp * 2],     ah[mi], bh);
                    mma_fp16(c[mi][njp * 2],     al[mi], bh);
                    mma_fp16(c[mi][njp * 2 + 1], ah[mi], bh + 2);
                    mma_fp16(c[mi][njp * 2 + 1], al[mi], bh + 2);
                }
            }
        }
        __syncthreads();
    }

    // epilogue: bias, row L2-norm across four warp_n quarters, scale, store
    int qr = lane >> 2;
    int qc = (lane & 3) * 2;
    float sq[2][2] = {{0.f, 0.f}, {0.f, 0.f}};
#pragma unroll
    for (int mi = 0; mi < 2; mi++)
#pragma unroll
        for (int nj = 0; nj < 4; nj++) {
            int colb = warp_n * 32 + nj * 8 + qc;
            float b0 = s_bias[colb], b1 = s_bias[colb + 1];
            c[mi][nj][0] += b0; c[mi][nj][1] += b1;
            c[mi][nj][2] += b0; c[mi][nj][3] += b1;
            sq[mi][0] += c[mi][nj][0] * c[mi][nj][0] + c[mi][nj][1] * c[mi][nj][1];
            sq[mi][1] += c[mi][nj][2] * c[mi][nj][2] + c[mi][nj][3] * c[mi][nj][3];
        }
#pragma unroll
    for (int mi = 0; mi < 2; mi++)
#pragma unroll
        for (int h = 0; h < 2; h++) {
            float v = sq[mi][h];
            v += __shfl_xor_sync(0xFFFFFFFFu, v, 1);
            v += __shfl_xor_sync(0xFFFFFFFFu, v, 2);
            if ((lane & 3) == 0)
                s_ssq[warp_m * 32 + mi * 16 + h * 8 + qr][warp_n] = v;
        }
    __syncthreads();
#pragma unroll
    for (int mi = 0; mi < 2; mi++)
#pragma unroll
        for (int h = 0; h < 2; h++) {
            int rloc = warp_m * 32 + mi * 16 + h * 8 + qr;
            float tot = s_ssq[rloc][0] + s_ssq[rloc][1] + s_ssq[rloc][2] + s_ssq[rloc][3];
            float s = SCALE / fmaxf(sqrtf(tot), 1e-12f);
            int gr = row0 + rloc;
            if (gr < N_NODES) {
                float* o = g_h + (size_t)gr * OUT_DIM + warp_n * 32 + qc;
#pragma unroll
                for (int nj = 0; nj < 4; nj++) {
                    float2 w2;
                    w2.x = c[mi][nj][h * 2] * s;
                    w2.y = c[mi][nj][h * 2 + 1] * s;
                    *(float2*)(o + nj * 8) = w2;
                }
            }
        }
}

// ---------------------------------------------------------------- gather rounds (measured-best form)
__global__ void __launch_bounds__(256) k_gather1() {
    int n = blockIdx.x * 8 + (threadIdx.x >> 5);
    int lane = threadIdx.x & 31;
    if (n >= N_NODES) return;

    int e0 = g_off[n], e1 = g_off[n + 1];
    float4 acc = make_float4(0.f, 0.f, 0.f, 0.f);
#pragma unroll 2
    for (int e = e0; e < e1; e++) {
        uint2 ed = g_edge[e];
        float w = __uint_as_float(ed.y);
        float4 v = __ldg((const float4*)(g_h + (size_t)ed.x * OUT_DIM) + lane);
        acc.x += w * v.x; acc.y += w * v.y; acc.z += w * v.z; acc.w += w * v.w;
    }
    float dn = g_dinv[n];
    float sc = ONE_MA * dn * dn + ALPHA;
    float4 hh = __ldg((const float4*)(g_h + (size_t)n * OUT_DIM) + lane);
    float4 o;
    o.x = ONE_MA * acc.x + sc * hh.x;
    o.y = ONE_MA * acc.y + sc * hh.y;
    o.z = ONE_MA * acc.z + sc * hh.z;
    o.w = ONE_MA * acc.w + sc * hh.w;
    *((float4*)(g_z + (size_t)n * OUT_DIM) + lane) = o;
}

__global__ void __launch_bounds__(256) k_gather2(float* __restrict__ out) {
    int n = blockIdx.x * 8 + (threadIdx.x >> 5);
    int lane = threadIdx.x & 31;
    if (n >= N_NODES) return;

    int e0 = g_off[n], e1 = g_off[n + 1];
    float4 acc = make_float4(0.f, 0.f, 0.f, 0.f);
#pragma unroll 2
    for (int e = e0; e < e1; e++) {
        uint2 ed = g_edge[e];
        float w = __uint_as_float(ed.y);
        float4 v = __ldg((const float4*)(g_z + (size_t)ed.x * OUT_DIM) + lane);
        acc.x += w * v.x; acc.y += w * v.y; acc.z += w * v.z; acc.w += w * v.w;
    }
    float dn = g_dinv[n];
    float sw = dn * dn;
    float4 cur = __ldg((const float4*)(g_z + (size_t)n * OUT_DIM) + lane);
    float4 hh  = __ldg((const float4*)(g_h + (size_t)n * OUT_DIM) + lane);
    float4 o;
    o.x = ONE_MA * (acc.x + sw * cur.x) + ALPHA * hh.x;
    o.y = ONE_MA * (acc.y + sw * cur.y) + ALPHA * hh.y;
    o.z = ONE_MA * (acc.z + sw * cur.z) + ALPHA * hh.z;
    o.w = ONE_MA * (acc.w + sw * cur.w) + ALPHA * hh.w;
    *((float4*)(out + (size_t)n * OUT_DIM) + lane) = o;
}

// ----------------------------------------------------------------
extern "C" void kernel_launch(void* const* d_in, const int* in_sizes, int n_in,
                              void* d_out, int out_size) {
    const float* x  = (const float*)d_in[0];
    const int*   ei = (const int*)d_in[1];
    const float* W  = (const float*)d_in[2];
    const float* b  = (const float*)d_in[3];
    float* out = (float*)d_out;

    // one-time side-stream + events + symbol address (host resources only)
    static cudaStream_t s2 = nullptr;
    static cudaEvent_t ev_fork = nullptr, ev_join = nullptr;
    static void* indeg_ptr = nullptr;
    if (s2 == nullptr) {
        cudaStreamCreateWithFlags(&s2, cudaStreamNonBlocking);
        cudaEventCreateWithFlags(&ev_fork, cudaEventDisableTiming);
        cudaEventCreateWithFlags(&ev_join, cudaEventDisableTiming);
        cudaGetSymbolAddress(&indeg_ptr, g_indeg);
    }

    // fork: CSR build on s2; W-convert + GEMM on the main (capture) stream
    cudaEventRecord(ev_fork, 0);
    cudaStreamWaitEvent(s2, ev_fork, 0);

    cudaMemsetAsync(indeg_ptr, 0, N_NODES * sizeof(int), s2);
    k_deg  <<<(E_EDGES / 2 + 255) / 256, 256, 0, s2>>>(ei);
    k_scan <<<1, 1024, 0, s2>>>();
    k_place<<<(E_EDGES / 2 + 255) / 256, 256, 0, s2>>>(ei);
    cudaEventRecord(ev_join, s2);

    k_wconv<<<(OUT_DIM * IN_DIM / 2 + 255) / 256, 256>>>(W);
    k_gemm_mma<<<(N_NODES + 63) / 64, 256>>>(x, b);

    // join: gathers need both the GEMM (g_h) and the CSR build
    cudaStreamWaitEvent(0, ev_join, 0);
    k_gather1<<<(N_NODES + 7) / 8, 256>>>();
    k_gather2<<<(N_NODES + 7) / 8, 256>>>(out);
}